// round 13
// baseline (speedup 1.0000x reference)
#include <cuda_runtime.h>
#include <cuda_fp16.h>
#include <cstdint>
#include <cstddef>

#define NN 100000
#define NPAD 100096   // 782 * 128
#define NE 1600000
#define C 128
#define NB_SCAN 98    // ceil(NN / 1024)

// ---------------- scratch (device globals) ----------------
__device__ int   g_deg[NN];
__device__ int   g_ptr[NN + 1];
__device__ float g_invc[NN];
__device__ int   g_csr[NE];
__device__ int   g_epos[NE];
__device__ int   g_bsum[128];

__device__ __half g_xf16 [(size_t)NPAD * C];
__device__ __half g_h1f16[(size_t)NPAD * C];
__device__ __half g_h2f16[(size_t)NPAD * C];

// weights fp16, [n][k] transposed; layer1/2 K=256 (Wl||Wr), decoder K=128
__device__ __half g_w1[128 * 256];
__device__ __half g_w2[128 * 256];
__device__ __half g_wd[128 * 128];

// ---------------- helpers ----------------
__device__ __forceinline__ uint32_t s2u(const void* p) {
    uint32_t a;
    asm("{ .reg .u64 t; cvta.to.shared.u64 t, %1; cvt.u32.u64 %0, t; }" : "=r"(a) : "l"(p));
    return a;
}
__device__ __forceinline__ void ldsm4(uint32_t* r, uint32_t addr) {
    asm volatile("ldmatrix.sync.aligned.m8n8.x4.shared.b16 {%0,%1,%2,%3}, [%4];"
                 : "=r"(r[0]), "=r"(r[1]), "=r"(r[2]), "=r"(r[3]) : "r"(addr));
}
__device__ __forceinline__ void mmaf16(float* d, const uint32_t* a, const uint32_t* b) {
    asm volatile(
        "mma.sync.aligned.m16n8k16.row.col.f32.f16.f16.f32 "
        "{%0,%1,%2,%3}, {%4,%5,%6,%7}, {%8,%9}, {%0,%1,%2,%3};"
        : "+f"(d[0]), "+f"(d[1]), "+f"(d[2]), "+f"(d[3])
        : "r"(a[0]), "r"(a[1]), "r"(a[2]), "r"(a[3]), "r"(b[0]), "r"(b[1]));
}
__device__ __forceinline__ uint32_t swz64(uint32_t off) {
    return off ^ ((off >> 3) & 0x30u);
}
__device__ __forceinline__ void cp16(uint32_t saddr, const void* gaddr) {
    asm volatile("cp.async.cg.shared.global [%0], [%1], 16;" :: "r"(saddr), "l"(gaddr));
}

// ---------------- CSR build ----------------
__global__ void count_kernel(const int4* __restrict__ dst4) {
    int i = blockIdx.x * blockDim.x + threadIdx.x;
    if (i < NE / 4) {
        int4 d = dst4[i];
        int4 p;
        p.x = atomicAdd(&g_deg[d.x], 1);
        p.y = atomicAdd(&g_deg[d.y], 1);
        p.z = atomicAdd(&g_deg[d.z], 1);
        p.w = atomicAdd(&g_deg[d.w], 1);
        ((int4*)g_epos)[i] = p;
    }
}
__global__ void scan1_kernel() {
    __shared__ int wsum[32];
    const int lane = threadIdx.x & 31;
    const int wid  = threadIdx.x >> 5;
    int i = blockIdx.x * 1024 + threadIdx.x;
    int v = (i < NN) ? g_deg[i] : 0;
    int incl = v;
    #pragma unroll
    for (int o = 1; o < 32; o <<= 1) {
        int t = __shfl_up_sync(0xFFFFFFFFu, incl, o);
        if (lane >= o) incl += t;
    }
    if (lane == 31) wsum[wid] = incl;
    __syncthreads();
    if (wid == 0) {
        int ws = wsum[lane];
        int wi = ws;
        #pragma unroll
        for (int o = 1; o < 32; o <<= 1) {
            int t = __shfl_up_sync(0xFFFFFFFFu, wi, o);
            if (lane >= o) wi += t;
        }
        wsum[lane] = wi - ws;
    }
    __syncthreads();
    int excl = wsum[wid] + incl - v;
    if (i < NN) g_ptr[i] = excl;
    if (threadIdx.x == 1023) g_bsum[blockIdx.x] = excl + v;
}
__global__ void scan2_kernel() {
    __shared__ int ws[4];
    const int t = threadIdx.x;
    const int lane = t & 31;
    const int wid  = t >> 5;
    int v = (t < NB_SCAN) ? g_bsum[t] : 0;
    int incl = v;
    #pragma unroll
    for (int o = 1; o < 32; o <<= 1) {
        int s = __shfl_up_sync(0xFFFFFFFFu, incl, o);
        if (lane >= o) incl += s;
    }
    if (lane == 31) ws[wid] = incl;
    __syncthreads();
    int add = 0;
    #pragma unroll
    for (int w = 0; w < 4; w++) if (w < wid) add += ws[w];
    int excl = add + incl - v;
    __syncthreads();
    if (t < NB_SCAN) g_bsum[t] = excl;
}
__global__ void scan3_kernel() {
    int i = blockIdx.x * 1024 + threadIdx.x;
    if (i == 0) g_ptr[NN] = NE;
    if (i < NN) {
        g_ptr[i] += g_bsum[blockIdx.x];
        int d = g_deg[i];
        g_invc[i] = 1.0f / (float)(d < 1 ? 1 : d);
    }
}
__global__ void build_kernel(const int4* __restrict__ src4, const int4* __restrict__ dst4) {
    int i = blockIdx.x * blockDim.x + threadIdx.x;
    if (i < NE / 4) {
        int4 s = src4[i];
        int4 d = dst4[i];
        int4 p = ((const int4*)g_epos)[i];
        g_csr[g_ptr[d.x] + p.x] = s.x;
        g_csr[g_ptr[d.y] + p.y] = s.y;
        g_csr[g_ptr[d.z] + p.z] = s.z;
        g_csr[g_ptr[d.w] + p.w] = s.w;
    }
}

// ---------------- fp32 -> fp16 for x ----------------
__global__ void split_kernel(const float* __restrict__ in, __half* __restrict__ f16) {
    int i = blockIdx.x * blockDim.x + threadIdx.x;
    if (i < NN * C / 4) {
        float4 v = ((const float4*)in)[i];
        ((__half2*)f16)[i * 2]     = __floats2half2_rn(v.x, v.y);
        ((__half2*)f16)[i * 2 + 1] = __floats2half2_rn(v.z, v.w);
    }
}

// ---------------- weight prep: fp16, grid (128, 3) ----------------
__global__ void wprep_kernel(const float* __restrict__ W1l, const float* __restrict__ W1r,
                             const float* __restrict__ W2l, const float* __restrict__ W2r,
                             const float* __restrict__ Wd) {
    const int n = blockIdx.x;
    const int which = blockIdx.y;
    const float* Wa; const float* Wb; __half* bh; int K;
    if (which == 0)      { Wa = W1l; Wb = W1r;     bh = g_w1; K = 256; }
    else if (which == 1) { Wa = W2l; Wb = W2r;     bh = g_w2; K = 256; }
    else                 { Wa = Wd;  Wb = nullptr; bh = g_wd; K = 128; }
    for (int k = threadIdx.x; k < K; k += blockDim.x) {
        float v = (k < C) ? Wa[k * C + n] : Wb[(k - C) * C + n];
        bh[n * K + k] = __float2half_rn(v);
    }
}

// ---------------- fused (agg + GEMM) layer kernel / decoder ----------------
// MODE 0 (layer, K=256): phase 1 gathers+means 128 node rows into SMEM agg
//   region (4 chunk-blocks of [128 x 64B], swz64, matching ldsm layout);
//   phase 2 MMA: chunks 0-3 A=agg SMEM, chunks 4-7 A=self rows (cp.async).
//   D = relu(agg@Wl + self@Wr + bias) -> fp16
// MODE 1 (decoder, K=128): no agg region; D = alpha*(A@B+bias)+(1-a)*x -> f32
// SMEM: MODE0: [0,32K) agg, [32K,32K+3*16K) stages. MODE1: 3*16K stages.
template <int MODE>
__global__ __launch_bounds__(256, 2) void gemm_f16_kernel(
    const __half* __restrict__ feat, const __half* __restrict__ B,
    const float* __restrict__ bias,
    const float* __restrict__ xres, const float* __restrict__ alphaPtr,
    float* __restrict__ outF, __half* __restrict__ outH)
{
    constexpr int K    = (MODE == 0) ? 256 : 128;
    constexpr int NCH  = K / 32;
    constexpr int BROW = K * 2;
    constexpr int STG  = 16384;
    constexpr int AGG  = (MODE == 0) ? 32768 : 0;
    extern __shared__ __align__(128) char smem[];
    const uint32_t us = s2u(smem);
    const uint32_t stage0 = us + AGG;

    const int tid  = threadIdx.x;
    const int wid  = tid >> 5;
    const int lane = tid & 31;
    const int m0   = blockIdx.x * 128;
    const int m0w  = (wid >> 1) * 32;
    const int n0w  = (wid & 1) * 64;

    const int lrow = tid >> 1;
    const int c16a = (tid & 1) * 2;

    auto issue = [&](int kc, int buf) {
        const uint32_t sb = stage0 + buf * STG;
        const bool doA = (MODE == 1) || (kc >= 4);
        const char* pA = (const char*)feat + (size_t)(m0 + lrow) * 256 + (kc & 3) * 64;
        const char* pB = (const char*)B + (size_t)lrow * BROW + kc * 64;
        #pragma unroll
        for (int j = 0; j < 2; j++) {
            const int c16 = c16a + j;
            const uint32_t so = swz64((uint32_t)(lrow * 64 + c16 * 16));
            if (doA) cp16(sb + so, pA + c16 * 16);
            cp16(sb + 8192 + so, pB + c16 * 16);
        }
        asm volatile("cp.async.commit_group;" ::: "memory");
    };

    // prefetch first two B (+A for decoder) chunks before the gather phase
    issue(0, 0);
    issue(1, 1);

    // ---------------- phase 1: inline aggregation (MODE 0) ----------------
    if (MODE == 0) {
        #pragma unroll 1
        for (int i = 0; i < 16; i++) {
            const int r = wid * 16 + i;
            const int grow = m0 + r;
            uint2 o = make_uint2(0u, 0u);
            if (grow < NN) {
                int beg = g_ptr[grow], end = g_ptr[grow + 1];
                float4 acc = make_float4(0.f, 0.f, 0.f, 0.f);
                int e = beg;
                for (; e + 8 <= end; e += 8) {
                    int idx[8];
                    #pragma unroll
                    for (int j = 0; j < 8; j++) idx[j] = g_csr[e + j];
                    uint2 u[8];
                    #pragma unroll
                    for (int j = 0; j < 8; j++)
                        u[j] = *reinterpret_cast<const uint2*>(
                            feat + (size_t)idx[j] * C + lane * 4);
                    #pragma unroll
                    for (int j = 0; j < 8; j++) {
                        float2 a = __half22float2(*(__half2*)&u[j].x);
                        float2 b = __half22float2(*(__half2*)&u[j].y);
                        acc.x += a.x; acc.y += a.y; acc.z += b.x; acc.w += b.y;
                    }
                }
                for (; e < end; e++) {
                    int s = g_csr[e];
                    uint2 uu = *reinterpret_cast<const uint2*>(
                        feat + (size_t)s * C + lane * 4);
                    float2 a = __half22float2(*(__half2*)&uu.x);
                    float2 b = __half22float2(*(__half2*)&uu.y);
                    acc.x += a.x; acc.y += a.y; acc.z += b.x; acc.w += b.y;
                }
                const float iv = g_invc[grow];
                __half2 o0 = __floats2half2_rn(acc.x * iv, acc.y * iv);
                __half2 o1 = __floats2half2_rn(acc.z * iv, acc.w * iv);
                o.x = *(uint32_t*)&o0; o.y = *(uint32_t*)&o1;
            }
            // store into chunk-major swizzled agg region (matches ldsm layout)
            const int chunk = lane >> 3;
            const uint32_t soff = swz64((uint32_t)(r * 64 + (lane & 7) * 8));
            *reinterpret_cast<uint2*>(smem + chunk * 8192 + soff) = o;
        }
    }
    __syncthreads();   // agg stores visible to all warps before ldsm

    // ---------------- phase 2: MMA mainloop ----------------
    float acc[2][8][4];
    #pragma unroll
    for (int i = 0; i < 2; i++)
        #pragma unroll
        for (int j = 0; j < 8; j++)
            #pragma unroll
            for (int q = 0; q < 4; q++) acc[i][j][q] = 0.f;

    #pragma unroll
    for (int kc = 0; kc < NCH; kc++) {
        if (kc + 1 < NCH) {
            asm volatile("cp.async.wait_group 1;" ::: "memory");
        } else {
            asm volatile("cp.async.wait_group 0;" ::: "memory");
        }
        __syncthreads();
        if (kc + 2 < NCH) issue(kc + 2, (kc + 2) % 3);
        const uint32_t sb = stage0 + (kc % 3) * STG;
        const uint32_t abase = (MODE == 0 && kc < 4) ? (us + kc * 8192) : sb;
        #pragma unroll
        for (int s = 0; s < 2; s++) {
            uint32_t aF[2][4], bb[4][4];
            #pragma unroll
            for (int sub = 0; sub < 2; sub++) {
                const uint32_t off = swz64((uint32_t)(
                    (m0w + sub * 16 + (lane & 15)) * 64 + s * 32 + (lane >> 4) * 16));
                ldsm4(aF[sub], abase + off);
            }
            #pragma unroll
            for (int p = 0; p < 4; p++) {
                const uint32_t off = swz64((uint32_t)(
                    (n0w + p * 16 + (lane & 7) + ((lane >> 4) << 3)) * 64 +
                    s * 32 + ((lane >> 3) & 1) * 16));
                ldsm4(bb[p], sb + 8192 + off);
            }
            #pragma unroll
            for (int sub = 0; sub < 2; sub++)
                #pragma unroll
                for (int p = 0; p < 4; p++) {
                    mmaf16(acc[sub][p * 2 + 0], aF[sub], &bb[p][0]);
                    mmaf16(acc[sub][p * 2 + 1], aF[sub], &bb[p][2]);
                }
        }
    }

    // ---------------- epilogue ----------------
    float al = 0.f, om = 0.f;
    if (MODE == 1) { al = *alphaPtr; om = 1.0f - al; }
    const int ccol0 = n0w + (lane & 3) * 2;
    #pragma unroll
    for (int sub = 0; sub < 2; sub++) {
        const int rbase = m0 + m0w + sub * 16 + (lane >> 2);
        #pragma unroll
        for (int f = 0; f < 8; f++) {
            const int col = ccol0 + f * 8;
            const float bx = bias[col], by = bias[col + 1];
            #pragma unroll
            for (int half = 0; half < 2; half++) {
                const int r = rbase + half * 8;
                if (r >= NN) continue;
                float vx = acc[sub][f][half * 2 + 0] + bx;
                float vy = acc[sub][f][half * 2 + 1] + by;
                if (MODE == 0) {
                    vx = fmaxf(vx, 0.f); vy = fmaxf(vy, 0.f);
                    *(__half2*)(outH + (size_t)r * C + col) = __floats2half2_rn(vx, vy);
                } else {
                    const float2 xr = *(const float2*)(xres + (size_t)r * C + col);
                    float2 fv;
                    fv.x = al * vx + om * xr.x;
                    fv.y = al * vy + om * xr.y;
                    *(float2*)(outF + (size_t)r * C + col) = fv;
                }
            }
        }
    }
}

// ---------------- launch ----------------
extern "C" void kernel_launch(void* const* d_in, const int* in_sizes, int n_in,
                              void* d_out, int out_size)
{
    const float* x    = (const float*)d_in[0];
    const int*   ei   = (const int*)  d_in[1];
    const float* W1l  = (const float*)d_in[2];
    const float* b1   = (const float*)d_in[3];
    const float* W1r  = (const float*)d_in[4];
    const float* W2l  = (const float*)d_in[5];
    const float* b2   = (const float*)d_in[6];
    const float* W2r  = (const float*)d_in[7];
    const float* Wd   = (const float*)d_in[8];
    const float* bd   = (const float*)d_in[9];
    const float* alph = (const float*)d_in[10];
    float* out = (float*)d_out;

    const int* src = ei;
    const int* dst = ei + NE;

    int* degp;
    __half *xf16, *h1f16, *h2f16;
    __half *w1, *w2, *wd;
    cudaGetSymbolAddress((void**)&degp,  g_deg);
    cudaGetSymbolAddress((void**)&xf16,  g_xf16);
    cudaGetSymbolAddress((void**)&h1f16, g_h1f16);
    cudaGetSymbolAddress((void**)&h2f16, g_h2f16);
    cudaGetSymbolAddress((void**)&w1,    g_w1);
    cudaGetSymbolAddress((void**)&w2,    g_w2);
    cudaGetSymbolAddress((void**)&wd,    g_wd);

    const int SMEM_L = 32768 + 3 * 16384;  // 80KB (fused layer)
    const int SMEM_D = 3 * 16384;          // 48KB (decoder)
    static bool attrSet = false;
    if (!attrSet) {
        cudaFuncSetAttribute(gemm_f16_kernel<0>, cudaFuncAttributeMaxDynamicSharedMemorySize, SMEM_L);
        cudaFuncSetAttribute(gemm_f16_kernel<1>, cudaFuncAttributeMaxDynamicSharedMemorySize, SMEM_D);
        attrSet = true;
    }

    const int TB = 256;
    const int gE4 = (NE / 4 + TB - 1) / TB;
    const int gM  = (NN + 127) / 128;
    const int gS  = (NN * C / 4 + TB - 1) / TB;

    cudaMemsetAsync(degp, 0, NN * sizeof(int));
    split_kernel<<<gS, TB>>>(x, xf16);
    wprep_kernel<<<dim3(128, 3), 256>>>(W1l, W1r, W2l, W2r, Wd);
    count_kernel<<<gE4, TB>>>((const int4*)dst);
    scan1_kernel<<<NB_SCAN, 1024>>>();
    scan2_kernel<<<1, 128>>>();
    scan3_kernel<<<NB_SCAN, 1024>>>();
    build_kernel<<<gE4, TB>>>((const int4*)src, (const int4*)dst);

    // layer 1: fused agg(x) + GEMM -> h1
    gemm_f16_kernel<0><<<gM, 256, SMEM_L>>>(xf16, w1, b1, nullptr, nullptr,
                                            nullptr, h1f16);
    // layer 2: fused agg(h1) + GEMM -> h2
    gemm_f16_kernel<0><<<gM, 256, SMEM_L>>>(h1f16, w2, b2, nullptr, nullptr,
                                            nullptr, h2f16);
    // decoder + residual blend
    gemm_f16_kernel<1><<<gM, 256, SMEM_D>>>(h2f16, wd, bd, x, alph,
                                            out, nullptr);

    (void)in_sizes; (void)n_in; (void)out_size;
}

// round 14
// speedup vs baseline: 1.3875x; 1.3875x over previous
#include <cuda_runtime.h>
#include <cuda_fp16.h>
#include <cstdint>
#include <cstddef>

#define NN 100000
#define NPAD 100096   // 782 * 128
#define NE 1600000
#define C 128
#define NB_SCAN 98    // ceil(NN / 1024)

// ---------------- scratch (device globals) ----------------
__device__ int   g_deg[NN];
__device__ int   g_ptr[NN + 1];
__device__ float g_invc[NN];
__device__ int   g_csr[NE];
__device__ int   g_epos[NE];
__device__ int   g_bsum[128];

__device__ __half g_xf16 [(size_t)NPAD * C];
__device__ __half g_h1f16[(size_t)NPAD * C];
__device__ __half g_h2f16[(size_t)NPAD * C];
__device__ __half g_aggf16[(size_t)NPAD * C];

// weights fp16, [n][k] transposed; layer1/2 K=256 (Wl||Wr), decoder K=128
__device__ __half g_w1[128 * 256];
__device__ __half g_w2[128 * 256];
__device__ __half g_wd[128 * 128];

// ---------------- helpers ----------------
__device__ __forceinline__ uint32_t s2u(const void* p) {
    uint32_t a;
    asm("{ .reg .u64 t; cvta.to.shared.u64 t, %1; cvt.u32.u64 %0, t; }" : "=r"(a) : "l"(p));
    return a;
}
__device__ __forceinline__ void ldsm4(uint32_t* r, uint32_t addr) {
    asm volatile("ldmatrix.sync.aligned.m8n8.x4.shared.b16 {%0,%1,%2,%3}, [%4];"
                 : "=r"(r[0]), "=r"(r[1]), "=r"(r[2]), "=r"(r[3]) : "r"(addr));
}
__device__ __forceinline__ void mmaf16(float* d, const uint32_t* a, const uint32_t* b) {
    asm volatile(
        "mma.sync.aligned.m16n8k16.row.col.f32.f16.f16.f32 "
        "{%0,%1,%2,%3}, {%4,%5,%6,%7}, {%8,%9}, {%0,%1,%2,%3};"
        : "+f"(d[0]), "+f"(d[1]), "+f"(d[2]), "+f"(d[3])
        : "r"(a[0]), "r"(a[1]), "r"(a[2]), "r"(a[3]), "r"(b[0]), "r"(b[1]));
}
__device__ __forceinline__ uint32_t swz64(uint32_t off) {
    return off ^ ((off >> 3) & 0x30u);
}
__device__ __forceinline__ void cp16(uint32_t saddr, const void* gaddr) {
    asm volatile("cp.async.cg.shared.global [%0], [%1], 16;" :: "r"(saddr), "l"(gaddr));
}
__device__ __forceinline__ void accv(float* a, uint4 v) {
    const __half2* h = (const __half2*)&v;
    #pragma unroll
    for (int q = 0; q < 4; q++) {
        float2 f = __half22float2(h[q]);
        a[2 * q]     += f.x;
        a[2 * q + 1] += f.y;
    }
}

// ---------------- CSR build ----------------
__global__ void count_kernel(const int4* __restrict__ dst4) {
    int i = blockIdx.x * blockDim.x + threadIdx.x;
    if (i < NE / 4) {
        int4 d = dst4[i];
        int4 p;
        p.x = atomicAdd(&g_deg[d.x], 1);
        p.y = atomicAdd(&g_deg[d.y], 1);
        p.z = atomicAdd(&g_deg[d.z], 1);
        p.w = atomicAdd(&g_deg[d.w], 1);
        ((int4*)g_epos)[i] = p;
    }
}
__global__ void scan1_kernel() {
    __shared__ int wsum[32];
    const int lane = threadIdx.x & 31;
    const int wid  = threadIdx.x >> 5;
    int i = blockIdx.x * 1024 + threadIdx.x;
    int v = (i < NN) ? g_deg[i] : 0;
    int incl = v;
    #pragma unroll
    for (int o = 1; o < 32; o <<= 1) {
        int t = __shfl_up_sync(0xFFFFFFFFu, incl, o);
        if (lane >= o) incl += t;
    }
    if (lane == 31) wsum[wid] = incl;
    __syncthreads();
    if (wid == 0) {
        int ws = wsum[lane];
        int wi = ws;
        #pragma unroll
        for (int o = 1; o < 32; o <<= 1) {
            int t = __shfl_up_sync(0xFFFFFFFFu, wi, o);
            if (lane >= o) wi += t;
        }
        wsum[lane] = wi - ws;
    }
    __syncthreads();
    int excl = wsum[wid] + incl - v;
    if (i < NN) g_ptr[i] = excl;
    if (threadIdx.x == 1023) g_bsum[blockIdx.x] = excl + v;
}
__global__ void scan2_kernel() {
    __shared__ int ws[4];
    const int t = threadIdx.x;
    const int lane = t & 31;
    const int wid  = t >> 5;
    int v = (t < NB_SCAN) ? g_bsum[t] : 0;
    int incl = v;
    #pragma unroll
    for (int o = 1; o < 32; o <<= 1) {
        int s = __shfl_up_sync(0xFFFFFFFFu, incl, o);
        if (lane >= o) incl += s;
    }
    if (lane == 31) ws[wid] = incl;
    __syncthreads();
    int add = 0;
    #pragma unroll
    for (int w = 0; w < 4; w++) if (w < wid) add += ws[w];
    int excl = add + incl - v;
    __syncthreads();
    if (t < NB_SCAN) g_bsum[t] = excl;
}
__global__ void scan3_kernel() {
    int i = blockIdx.x * 1024 + threadIdx.x;
    if (i == 0) g_ptr[NN] = NE;
    if (i < NN) {
        g_ptr[i] += g_bsum[blockIdx.x];
        int d = g_deg[i];
        g_invc[i] = 1.0f / (float)(d < 1 ? 1 : d);
    }
}
__global__ void build_kernel(const int4* __restrict__ src4, const int4* __restrict__ dst4) {
    int i = blockIdx.x * blockDim.x + threadIdx.x;
    if (i < NE / 4) {
        int4 s = src4[i];
        int4 d = dst4[i];
        int4 p = ((const int4*)g_epos)[i];
        g_csr[g_ptr[d.x] + p.x] = s.x;
        g_csr[g_ptr[d.y] + p.y] = s.y;
        g_csr[g_ptr[d.z] + p.z] = s.z;
        g_csr[g_ptr[d.w] + p.w] = s.w;
    }
}

// ---------------- fp32 -> fp16 for x ----------------
__global__ void split_kernel(const float* __restrict__ in, __half* __restrict__ f16) {
    int i = blockIdx.x * blockDim.x + threadIdx.x;
    if (i < NN * C / 4) {
        float4 v = ((const float4*)in)[i];
        ((__half2*)f16)[i * 2]     = __floats2half2_rn(v.x, v.y);
        ((__half2*)f16)[i * 2 + 1] = __floats2half2_rn(v.z, v.w);
    }
}

// ---------------- weight prep: fp16, grid (128, 3) ----------------
__global__ void wprep_kernel(const float* __restrict__ W1l, const float* __restrict__ W1r,
                             const float* __restrict__ W2l, const float* __restrict__ W2r,
                             const float* __restrict__ Wd) {
    const int n = blockIdx.x;
    const int which = blockIdx.y;
    const float* Wa; const float* Wb; __half* bh; int K;
    if (which == 0)      { Wa = W1l; Wb = W1r;     bh = g_w1; K = 256; }
    else if (which == 1) { Wa = W2l; Wb = W2r;     bh = g_w2; K = 256; }
    else                 { Wa = Wd;  Wb = nullptr; bh = g_wd; K = 128; }
    for (int k = threadIdx.x; k < K; k += blockDim.x) {
        float v = (k < C) ? Wa[k * C + n] : Wb[(k - C) * C + n];
        bh[n * K + k] = __float2half_rn(v);
    }
}

// ---------------- aggregation v3: HALF-WARP per node, uint4 lanes, 8-edge unroll ----------------
__global__ void agg_kernel(const __half* __restrict__ feat, __half* __restrict__ outp) {
    int g = (blockIdx.x * blockDim.x + threadIdx.x) >> 4;   // half-warp id = node
    if (g >= NN) return;
    const int li = threadIdx.x & 15;    // 16 lanes x 16B = 256B row
    int beg = g_ptr[g], end = g_ptr[g + 1];
    float acc[8];
    #pragma unroll
    for (int j = 0; j < 8; j++) acc[j] = 0.f;

    int e = beg;
    for (; e + 8 <= end; e += 8) {
        int idx[8];
        #pragma unroll
        for (int j = 0; j < 8; j++) idx[j] = g_csr[e + j];
        uint4 v[8];
        #pragma unroll
        for (int j = 0; j < 8; j++)
            v[j] = *((const uint4*)(feat + (size_t)idx[j] * C) + li);
        #pragma unroll
        for (int j = 0; j < 8; j++) accv(acc, v[j]);
    }
    for (; e < end; e++) {
        int s = g_csr[e];
        uint4 v = *((const uint4*)(feat + (size_t)s * C) + li);
        accv(acc, v);
    }

    const float iv = g_invc[g];
    uint4 o;
    __half2* oh = (__half2*)&o;
    #pragma unroll
    for (int q = 0; q < 4; q++)
        oh[q] = __floats2half2_rn(acc[2 * q] * iv, acc[2 * q + 1] * iv);
    *((uint4*)(outp + (size_t)g * C) + li) = o;
}

// ---------------- fp16 single-product GEMM, 3-stage cp.async, 1 barrier/chunk ----------------
// D[128,128] = A[128,K] @ B^T, fp32 accum.
// MODE 0: layer   (K=256, A1=agg, A2=self) -> relu(acc + bias) -> fp16
// MODE 1: decoder (K=128, A1=h2)           -> alpha*(acc+bias)+(1-alpha)*xres -> f32
// Stage: A[0,8K) B[8K,16K); 64B rows, swz64; 3 stages (48KB).
template <int MODE>
__global__ __launch_bounds__(256, 2) void gemm_f16_kernel(
    const __half* __restrict__ A1, const __half* __restrict__ A2,
    const __half* __restrict__ B,
    const float* __restrict__ bias,
    const float* __restrict__ xres, const float* __restrict__ alphaPtr,
    float* __restrict__ outF, __half* __restrict__ outH)
{
    constexpr int K    = (MODE == 0) ? 256 : 128;
    constexpr int NCH  = K / 32;
    constexpr int BROW = K * 2;
    constexpr int STG  = 16384;
    extern __shared__ __align__(128) char smem[];
    const uint32_t us = s2u(smem);

    const int tid  = threadIdx.x;
    const int wid  = tid >> 5;
    const int lane = tid & 31;
    const int m0   = blockIdx.x * 128;
    const int m0w  = (wid >> 1) * 32;
    const int n0w  = (wid & 1) * 64;

    const int lrow = tid >> 1;
    const int c16a = (tid & 1) * 2;

    float acc[2][8][4];
    #pragma unroll
    for (int i = 0; i < 2; i++)
        #pragma unroll
        for (int j = 0; j < 8; j++)
            #pragma unroll
            for (int q = 0; q < 4; q++) acc[i][j][q] = 0.f;

    auto issue = [&](int kc, int buf) {
        const __half* sA = (MODE == 0 && kc >= 4) ? A2 : A1;
        const char* pA = (const char*)sA + (size_t)(m0 + lrow) * 256 + (kc & 3) * 64;
        const char* pB = (const char*)B + (size_t)lrow * BROW + kc * 64;
        const uint32_t sb = us + buf * STG;
        #pragma unroll
        for (int j = 0; j < 2; j++) {
            const int c16 = c16a + j;
            const uint32_t so = swz64((uint32_t)(lrow * 64 + c16 * 16));
            cp16(sb + so,        pA + c16 * 16);
            cp16(sb + 8192 + so, pB + c16 * 16);
        }
        asm volatile("cp.async.commit_group;" ::: "memory");
    };

    issue(0, 0);
    issue(1, 1);
    #pragma unroll
    for (int kc = 0; kc < NCH; kc++) {
        if (kc + 1 < NCH) {
            asm volatile("cp.async.wait_group 1;" ::: "memory");
        } else {
            asm volatile("cp.async.wait_group 0;" ::: "memory");
        }
        __syncthreads();
        if (kc + 2 < NCH) issue(kc + 2, (kc + 2) % 3);
        const uint32_t sb = us + (kc % 3) * STG;
        #pragma unroll
        for (int s = 0; s < 2; s++) {
            uint32_t aF[2][4], bb[4][4];
            #pragma unroll
            for (int sub = 0; sub < 2; sub++) {
                const uint32_t off = swz64((uint32_t)(
                    (m0w + sub * 16 + (lane & 15)) * 64 + s * 32 + (lane >> 4) * 16));
                ldsm4(aF[sub], sb + off);
            }
            #pragma unroll
            for (int p = 0; p < 4; p++) {
                const uint32_t off = swz64((uint32_t)(
                    (n0w + p * 16 + (lane & 7) + ((lane >> 4) << 3)) * 64 +
                    s * 32 + ((lane >> 3) & 1) * 16));
                ldsm4(bb[p], sb + 8192 + off);
            }
            #pragma unroll
            for (int sub = 0; sub < 2; sub++)
                #pragma unroll
                for (int p = 0; p < 4; p++) {
                    mmaf16(acc[sub][p * 2 + 0], aF[sub], &bb[p][0]);
                    mmaf16(acc[sub][p * 2 + 1], aF[sub], &bb[p][2]);
                }
        }
    }

    // ---------------- epilogue ----------------
    float al = 0.f, om = 0.f;
    if (MODE == 1) { al = *alphaPtr; om = 1.0f - al; }
    const int ccol0 = n0w + (lane & 3) * 2;
    #pragma unroll
    for (int sub = 0; sub < 2; sub++) {
        const int rbase = m0 + m0w + sub * 16 + (lane >> 2);
        #pragma unroll
        for (int f = 0; f < 8; f++) {
            const int col = ccol0 + f * 8;
            const float bx = bias[col], by = bias[col + 1];
            #pragma unroll
            for (int half = 0; half < 2; half++) {
                const int r = rbase + half * 8;
                if (r >= NN) continue;
                float vx = acc[sub][f][half * 2 + 0] + bx;
                float vy = acc[sub][f][half * 2 + 1] + by;
                if (MODE == 0) {
                    vx = fmaxf(vx, 0.f); vy = fmaxf(vy, 0.f);
                    *(__half2*)(outH + (size_t)r * C + col) = __floats2half2_rn(vx, vy);
                } else {
                    const float2 xr = *(const float2*)(xres + (size_t)r * C + col);
                    float2 fv;
                    fv.x = al * vx + om * xr.x;
                    fv.y = al * vy + om * xr.y;
                    *(float2*)(outF + (size_t)r * C + col) = fv;
                }
            }
        }
    }
}

// ---------------- launch ----------------
extern "C" void kernel_launch(void* const* d_in, const int* in_sizes, int n_in,
                              void* d_out, int out_size)
{
    const float* x    = (const float*)d_in[0];
    const int*   ei   = (const int*)  d_in[1];
    const float* W1l  = (const float*)d_in[2];
    const float* b1   = (const float*)d_in[3];
    const float* W1r  = (const float*)d_in[4];
    const float* W2l  = (const float*)d_in[5];
    const float* b2   = (const float*)d_in[6];
    const float* W2r  = (const float*)d_in[7];
    const float* Wd   = (const float*)d_in[8];
    const float* bd   = (const float*)d_in[9];
    const float* alph = (const float*)d_in[10];
    float* out = (float*)d_out;

    const int* src = ei;
    const int* dst = ei + NE;

    int* degp;
    __half *xf16, *h1f16, *h2f16, *aggf16;
    __half *w1, *w2, *wd;
    cudaGetSymbolAddress((void**)&degp,  g_deg);
    cudaGetSymbolAddress((void**)&xf16,  g_xf16);
    cudaGetSymbolAddress((void**)&h1f16, g_h1f16);
    cudaGetSymbolAddress((void**)&h2f16, g_h2f16);
    cudaGetSymbolAddress((void**)&aggf16,g_aggf16);
    cudaGetSymbolAddress((void**)&w1,    g_w1);
    cudaGetSymbolAddress((void**)&w2,    g_w2);
    cudaGetSymbolAddress((void**)&wd,    g_wd);

    const int SMEM_GEMM = 3 * 16384;  // 48KB
    static bool attrSet = false;
    if (!attrSet) {
        cudaFuncSetAttribute(gemm_f16_kernel<0>, cudaFuncAttributeMaxDynamicSharedMemorySize, SMEM_GEMM);
        cudaFuncSetAttribute(gemm_f16_kernel<1>, cudaFuncAttributeMaxDynamicSharedMemorySize, SMEM_GEMM);
        attrSet = true;
    }

    const int TB = 256;
    const int gE4 = (NE / 4 + TB - 1) / TB;
    const int gAg = (NN * 16 + TB - 1) / TB;   // half-warp per node
    const int gM  = (NN + 127) / 128;
    const int gS  = (NN * C / 4 + TB - 1) / TB;

    cudaMemsetAsync(degp, 0, NN * sizeof(int));
    split_kernel<<<gS, TB>>>(x, xf16);
    wprep_kernel<<<dim3(128, 3), 256>>>(W1l, W1r, W2l, W2r, Wd);
    count_kernel<<<gE4, TB>>>((const int4*)dst);
    scan1_kernel<<<NB_SCAN, 1024>>>();
    scan2_kernel<<<1, 128>>>();
    scan3_kernel<<<NB_SCAN, 1024>>>();
    build_kernel<<<gE4, TB>>>((const int4*)src, (const int4*)dst);

    // layer 1 (fused K=256)
    agg_kernel<<<gAg, TB>>>(xf16, aggf16);
    gemm_f16_kernel<0><<<gM, 256, SMEM_GEMM>>>(aggf16, xf16, w1,
                                               b1, nullptr, nullptr,
                                               nullptr, h1f16);
    // layer 2 (fused K=256)
    agg_kernel<<<gAg, TB>>>(h1f16, aggf16);
    gemm_f16_kernel<0><<<gM, 256, SMEM_GEMM>>>(aggf16, h1f16, w2,
                                               b2, nullptr, nullptr,
                                               nullptr, h2f16);
    // decoder + residual blend
    gemm_f16_kernel<1><<<gM, 256, SMEM_GEMM>>>(h2f16, nullptr, wd,
                                               bd, x, alph,
                                               out, nullptr);

    (void)in_sizes; (void)n_in; (void)out_size;
}

// round 15
// speedup vs baseline: 1.4149x; 1.0198x over previous
#include <cuda_runtime.h>
#include <cuda_fp16.h>
#include <cstdint>
#include <cstddef>

#define NN 100000
#define NPAD 100096   // 782 * 128
#define NE 1600000
#define C 128
#define NB_SCAN 98    // ceil(NN / 1024)

#define GB_COUNT 1563    // ceil(NE/4 / 256)
#define GB_SPLIT 12500   // NN*C/4 / 256
#define GB_WPREP 384     // 3 * 128

// ---------------- scratch (device globals; zero-init at load) ----------------
__device__ int   g_deg[NN];      // invariant: zero at kernel_launch entry
__device__ int   g_ptr[NN + 1];
__device__ float g_invc[NN];
__device__ int   g_csr[NE];
__device__ int   g_epos[NE];
__device__ int   g_bsum[128];

__device__ __half g_xf16 [(size_t)NPAD * C];
__device__ __half g_h1f16[(size_t)NPAD * C];
__device__ __half g_h2f16[(size_t)NPAD * C];
__device__ __half g_aggf16[(size_t)NPAD * C];

// weights fp16, [n][k] transposed; layer1/2 K=256 (Wl||Wr), decoder K=128
__device__ __half g_w1[128 * 256];
__device__ __half g_w2[128 * 256];
__device__ __half g_wd[128 * 128];

// ---------------- helpers ----------------
__device__ __forceinline__ uint32_t s2u(const void* p) {
    uint32_t a;
    asm("{ .reg .u64 t; cvta.to.shared.u64 t, %1; cvt.u32.u64 %0, t; }" : "=r"(a) : "l"(p));
    return a;
}
__device__ __forceinline__ void ldsm4(uint32_t* r, uint32_t addr) {
    asm volatile("ldmatrix.sync.aligned.m8n8.x4.shared.b16 {%0,%1,%2,%3}, [%4];"
                 : "=r"(r[0]), "=r"(r[1]), "=r"(r[2]), "=r"(r[3]) : "r"(addr));
}
__device__ __forceinline__ void mmaf16(float* d, const uint32_t* a, const uint32_t* b) {
    asm volatile(
        "mma.sync.aligned.m16n8k16.row.col.f32.f16.f16.f32 "
        "{%0,%1,%2,%3}, {%4,%5,%6,%7}, {%8,%9}, {%0,%1,%2,%3};"
        : "+f"(d[0]), "+f"(d[1]), "+f"(d[2]), "+f"(d[3])
        : "r"(a[0]), "r"(a[1]), "r"(a[2]), "r"(a[3]), "r"(b[0]), "r"(b[1]));
}
__device__ __forceinline__ uint32_t swz64(uint32_t off) {
    return off ^ ((off >> 3) & 0x30u);
}
__device__ __forceinline__ void cp16(uint32_t saddr, const void* gaddr) {
    asm volatile("cp.async.cg.shared.global [%0], [%1], 16;" :: "r"(saddr), "l"(gaddr));
}
__device__ __forceinline__ void accv(float* a, uint4 v) {
    const __half2* h = (const __half2*)&v;
    #pragma unroll
    for (int q = 0; q < 4; q++) {
        float2 f = __half22float2(h[q]);
        a[2 * q]     += f.x;
        a[2 * q + 1] += f.y;
    }
}

// ---------------- fused prep: count (+epos) | split x->fp16 | weight transpose ----------------
__global__ void prep_kernel(const float* __restrict__ x, __half* __restrict__ xf16,
                            const float* __restrict__ W1l, const float* __restrict__ W1r,
                            const float* __restrict__ W2l, const float* __restrict__ W2r,
                            const float* __restrict__ Wd,
                            const int4* __restrict__ dst4) {
    const int bx = blockIdx.x;
    if (bx < GB_COUNT) {
        int i = bx * 256 + threadIdx.x;
        if (i < NE / 4) {
            int4 d = dst4[i];
            int4 p;
            p.x = atomicAdd(&g_deg[d.x], 1);
            p.y = atomicAdd(&g_deg[d.y], 1);
            p.z = atomicAdd(&g_deg[d.z], 1);
            p.w = atomicAdd(&g_deg[d.w], 1);
            ((int4*)g_epos)[i] = p;
        }
    } else if (bx < GB_COUNT + GB_SPLIT) {
        int i = (bx - GB_COUNT) * 256 + threadIdx.x;
        if (i < NN * C / 4) {
            float4 v = ((const float4*)x)[i];
            ((__half2*)xf16)[i * 2]     = __floats2half2_rn(v.x, v.y);
            ((__half2*)xf16)[i * 2 + 1] = __floats2half2_rn(v.z, v.w);
        }
    } else {
        const int idx = bx - GB_COUNT - GB_SPLIT;  // 0..383
        const int which = idx >> 7;
        const int n = idx & 127;
        const float* Wa; const float* Wb; __half* bh; int K;
        if (which == 0)      { Wa = W1l; Wb = W1r;     bh = g_w1; K = 256; }
        else if (which == 1) { Wa = W2l; Wb = W2r;     bh = g_w2; K = 256; }
        else                 { Wa = Wd;  Wb = nullptr; bh = g_wd; K = 128; }
        for (int k = threadIdx.x; k < K; k += blockDim.x) {
            float v = (k < C) ? Wa[k * C + n] : Wb[(k - C) * C + n];
            bh[n * K + k] = __float2half_rn(v);
        }
    }
}

// ---------------- CSR scans ----------------
__global__ void scan1_kernel() {
    __shared__ int wsum[32];
    const int lane = threadIdx.x & 31;
    const int wid  = threadIdx.x >> 5;
    int i = blockIdx.x * 1024 + threadIdx.x;
    int v = (i < NN) ? g_deg[i] : 0;
    int incl = v;
    #pragma unroll
    for (int o = 1; o < 32; o <<= 1) {
        int t = __shfl_up_sync(0xFFFFFFFFu, incl, o);
        if (lane >= o) incl += t;
    }
    if (lane == 31) wsum[wid] = incl;
    __syncthreads();
    if (wid == 0) {
        int ws = wsum[lane];
        int wi = ws;
        #pragma unroll
        for (int o = 1; o < 32; o <<= 1) {
            int t = __shfl_up_sync(0xFFFFFFFFu, wi, o);
            if (lane >= o) wi += t;
        }
        wsum[lane] = wi - ws;
    }
    __syncthreads();
    int excl = wsum[wid] + incl - v;
    if (i < NN) g_ptr[i] = excl;
    if (threadIdx.x == 1023) g_bsum[blockIdx.x] = excl + v;
}
__global__ void scan2_kernel() {
    __shared__ int ws[4];
    const int t = threadIdx.x;
    const int lane = t & 31;
    const int wid  = t >> 5;
    int v = (t < NB_SCAN) ? g_bsum[t] : 0;
    int incl = v;
    #pragma unroll
    for (int o = 1; o < 32; o <<= 1) {
        int s = __shfl_up_sync(0xFFFFFFFFu, incl, o);
        if (lane >= o) incl += s;
    }
    if (lane == 31) ws[wid] = incl;
    __syncthreads();
    int add = 0;
    #pragma unroll
    for (int w = 0; w < 4; w++) if (w < wid) add += ws[w];
    int excl = add + incl - v;
    __syncthreads();
    if (t < NB_SCAN) g_bsum[t] = excl;
}
// adds block offsets, computes invc, and RE-ZEROES g_deg (invariant for next call)
__global__ void scan3_kernel() {
    int i = blockIdx.x * 1024 + threadIdx.x;
    if (i == 0) g_ptr[NN] = NE;
    if (i < NN) {
        g_ptr[i] += g_bsum[blockIdx.x];
        int d = g_deg[i];
        g_invc[i] = 1.0f / (float)(d < 1 ? 1 : d);
        g_deg[i] = 0;
    }
}
__global__ void build_kernel(const int4* __restrict__ src4, const int4* __restrict__ dst4) {
    int i = blockIdx.x * blockDim.x + threadIdx.x;
    if (i < NE / 4) {
        int4 s = src4[i];
        int4 d = dst4[i];
        int4 p = ((const int4*)g_epos)[i];
        g_csr[g_ptr[d.x] + p.x] = s.x;
        g_csr[g_ptr[d.y] + p.y] = s.y;
        g_csr[g_ptr[d.z] + p.z] = s.z;
        g_csr[g_ptr[d.w] + p.w] = s.w;
    }
}

// ---------------- aggregation: half-warp per node, uint4 lanes, 8-edge unroll ----------------
__global__ void agg_kernel(const __half* __restrict__ feat, __half* __restrict__ outp) {
    int g = (blockIdx.x * blockDim.x + threadIdx.x) >> 4;
    if (g >= NN) return;
    const int li = threadIdx.x & 15;
    int beg = g_ptr[g], end = g_ptr[g + 1];
    float acc[8];
    #pragma unroll
    for (int j = 0; j < 8; j++) acc[j] = 0.f;

    int e = beg;
    for (; e + 8 <= end; e += 8) {
        int idx[8];
        #pragma unroll
        for (int j = 0; j < 8; j++) idx[j] = g_csr[e + j];
        uint4 v[8];
        #pragma unroll
        for (int j = 0; j < 8; j++)
            v[j] = *((const uint4*)(feat + (size_t)idx[j] * C) + li);
        #pragma unroll
        for (int j = 0; j < 8; j++) accv(acc, v[j]);
    }
    for (; e < end; e++) {
        int s = g_csr[e];
        uint4 v = *((const uint4*)(feat + (size_t)s * C) + li);
        accv(acc, v);
    }

    const float iv = g_invc[g];
    uint4 o;
    __half2* oh = (__half2*)&o;
    #pragma unroll
    for (int q = 0; q < 4; q++)
        oh[q] = __floats2half2_rn(acc[2 * q] * iv, acc[2 * q + 1] * iv);
    *((uint4*)(outp + (size_t)g * C) + li) = o;
}

// ---------------- fp16 GEMM, 4-stage cp.async, 1 barrier/chunk ----------------
// MODE 0: layer   (K=256, A1=agg, A2=self) -> relu(acc + bias) -> fp16
// MODE 1: decoder (K=128, A1=h2)           -> alpha*(acc+bias)+(1-alpha)*xres -> f32
// Stage: A[0,8K) B[8K,16K); 64B rows, swz64; 4 stages (64KB).
template <int MODE>
__global__ __launch_bounds__(256, 2) void gemm_f16_kernel(
    const __half* __restrict__ A1, const __half* __restrict__ A2,
    const __half* __restrict__ B,
    const float* __restrict__ bias,
    const float* __restrict__ xres, const float* __restrict__ alphaPtr,
    float* __restrict__ outF, __half* __restrict__ outH)
{
    constexpr int K    = (MODE == 0) ? 256 : 128;
    constexpr int NCH  = K / 32;
    constexpr int BROW = K * 2;
    constexpr int STG  = 16384;
    extern __shared__ __align__(128) char smem[];
    const uint32_t us = s2u(smem);

    const int tid  = threadIdx.x;
    const int wid  = tid >> 5;
    const int lane = tid & 31;
    const int m0   = blockIdx.x * 128;
    const int m0w  = (wid >> 1) * 32;
    const int n0w  = (wid & 1) * 64;

    const int lrow = tid >> 1;
    const int c16a = (tid & 1) * 2;

    float acc[2][8][4];
    #pragma unroll
    for (int i = 0; i < 2; i++)
        #pragma unroll
        for (int j = 0; j < 8; j++)
            #pragma unroll
            for (int q = 0; q < 4; q++) acc[i][j][q] = 0.f;

    auto issue = [&](int kc, int buf) {
        const __half* sA = (MODE == 0 && kc >= 4) ? A2 : A1;
        const char* pA = (const char*)sA + (size_t)(m0 + lrow) * 256 + (kc & 3) * 64;
        const char* pB = (const char*)B + (size_t)lrow * BROW + kc * 64;
        const uint32_t sb = us + buf * STG;
        #pragma unroll
        for (int j = 0; j < 2; j++) {
            const int c16 = c16a + j;
            const uint32_t so = swz64((uint32_t)(lrow * 64 + c16 * 16));
            cp16(sb + so,        pA + c16 * 16);
            cp16(sb + 8192 + so, pB + c16 * 16);
        }
        asm volatile("cp.async.commit_group;" ::: "memory");
    };

    issue(0, 0);
    issue(1, 1);
    if (NCH > 2) issue(2, 2);
    #pragma unroll
    for (int kc = 0; kc < NCH; kc++) {
        if (kc + 2 < NCH) {
            asm volatile("cp.async.wait_group 2;" ::: "memory");
        } else if (kc + 1 < NCH) {
            asm volatile("cp.async.wait_group 1;" ::: "memory");
        } else {
            asm volatile("cp.async.wait_group 0;" ::: "memory");
        }
        __syncthreads();
        if (kc + 3 < NCH) issue(kc + 3, (kc + 3) & 3);
        const uint32_t sb = us + (kc & 3) * STG;
        #pragma unroll
        for (int s = 0; s < 2; s++) {
            uint32_t aF[2][4], bb[4][4];
            #pragma unroll
            for (int sub = 0; sub < 2; sub++) {
                const uint32_t off = swz64((uint32_t)(
                    (m0w + sub * 16 + (lane & 15)) * 64 + s * 32 + (lane >> 4) * 16));
                ldsm4(aF[sub], sb + off);
            }
            #pragma unroll
            for (int p = 0; p < 4; p++) {
                const uint32_t off = swz64((uint32_t)(
                    (n0w + p * 16 + (lane & 7) + ((lane >> 4) << 3)) * 64 +
                    s * 32 + ((lane >> 3) & 1) * 16));
                ldsm4(bb[p], sb + 8192 + off);
            }
            #pragma unroll
            for (int sub = 0; sub < 2; sub++)
                #pragma unroll
                for (int p = 0; p < 4; p++) {
                    mmaf16(acc[sub][p * 2 + 0], aF[sub], &bb[p][0]);
                    mmaf16(acc[sub][p * 2 + 1], aF[sub], &bb[p][2]);
                }
        }
    }

    // ---------------- epilogue ----------------
    float al = 0.f, om = 0.f;
    if (MODE == 1) { al = *alphaPtr; om = 1.0f - al; }
    const int ccol0 = n0w + (lane & 3) * 2;
    #pragma unroll
    for (int sub = 0; sub < 2; sub++) {
        const int rbase = m0 + m0w + sub * 16 + (lane >> 2);
        #pragma unroll
        for (int f = 0; f < 8; f++) {
            const int col = ccol0 + f * 8;
            const float bx = bias[col], by = bias[col + 1];
            #pragma unroll
            for (int half = 0; half < 2; half++) {
                const int r = rbase + half * 8;
                if (r >= NN) continue;
                float vx = acc[sub][f][half * 2 + 0] + bx;
                float vy = acc[sub][f][half * 2 + 1] + by;
                if (MODE == 0) {
                    vx = fmaxf(vx, 0.f); vy = fmaxf(vy, 0.f);
                    *(__half2*)(outH + (size_t)r * C + col) = __floats2half2_rn(vx, vy);
                } else {
                    const float2 xr = *(const float2*)(xres + (size_t)r * C + col);
                    float2 fv;
                    fv.x = al * vx + om * xr.x;
                    fv.y = al * vy + om * xr.y;
                    *(float2*)(outF + (size_t)r * C + col) = fv;
                }
            }
        }
    }
}

// ---------------- launch ----------------
extern "C" void kernel_launch(void* const* d_in, const int* in_sizes, int n_in,
                              void* d_out, int out_size)
{
    const float* x    = (const float*)d_in[0];
    const int*   ei   = (const int*)  d_in[1];
    const float* W1l  = (const float*)d_in[2];
    const float* b1   = (const float*)d_in[3];
    const float* W1r  = (const float*)d_in[4];
    const float* W2l  = (const float*)d_in[5];
    const float* b2   = (const float*)d_in[6];
    const float* W2r  = (const float*)d_in[7];
    const float* Wd   = (const float*)d_in[8];
    const float* bd   = (const float*)d_in[9];
    const float* alph = (const float*)d_in[10];
    float* out = (float*)d_out;

    const int* src = ei;
    const int* dst = ei + NE;

    __half *xf16, *h1f16, *h2f16, *aggf16;
    __half *w1, *w2, *wd;
    cudaGetSymbolAddress((void**)&xf16,  g_xf16);
    cudaGetSymbolAddress((void**)&h1f16, g_h1f16);
    cudaGetSymbolAddress((void**)&h2f16, g_h2f16);
    cudaGetSymbolAddress((void**)&aggf16,g_aggf16);
    cudaGetSymbolAddress((void**)&w1,    g_w1);
    cudaGetSymbolAddress((void**)&w2,    g_w2);
    cudaGetSymbolAddress((void**)&wd,    g_wd);

    const int SMEM_GEMM = 4 * 16384;  // 64KB
    static bool attrSet = false;
    if (!attrSet) {
        cudaFuncSetAttribute(gemm_f16_kernel<0>, cudaFuncAttributeMaxDynamicSharedMemorySize, SMEM_GEMM);
        cudaFuncSetAttribute(gemm_f16_kernel<1>, cudaFuncAttributeMaxDynamicSharedMemorySize, SMEM_GEMM);
        attrSet = true;
    }

    const int TB = 256;
    const int gE4 = (NE / 4 + TB - 1) / TB;
    const int gAg = (NN * 16 + TB - 1) / TB;
    const int gM  = (NN + 127) / 128;

    // fused prep: count (atomics) || split x->fp16 || weight transpose
    prep_kernel<<<GB_COUNT + GB_SPLIT + GB_WPREP, TB>>>(
        x, xf16, W1l, W1r, W2l, W2r, Wd, (const int4*)dst);
    scan1_kernel<<<NB_SCAN, 1024>>>();
    scan2_kernel<<<1, 128>>>();
    scan3_kernel<<<NB_SCAN, 1024>>>();
    build_kernel<<<gE4, TB>>>((const int4*)src, (const int4*)dst);

    // layer 1 (fused K=256)
    agg_kernel<<<gAg, TB>>>(xf16, aggf16);
    gemm_f16_kernel<0><<<gM, 256, SMEM_GEMM>>>(aggf16, xf16, w1,
                                               b1, nullptr, nullptr,
                                               nullptr, h1f16);
    // layer 2 (fused K=256)
    agg_kernel<<<gAg, TB>>>(h1f16, aggf16);
    gemm_f16_kernel<0><<<gM, 256, SMEM_GEMM>>>(aggf16, h1f16, w2,
                                               b2, nullptr, nullptr,
                                               nullptr, h2f16);
    // decoder + residual blend
    gemm_f16_kernel<1><<<gM, 256, SMEM_GEMM>>>(h2f16, nullptr, wd,
                                               bd, x, alph,
                                               out, nullptr);

    (void)in_sizes; (void)n_in; (void)out_size;
}

// round 16
// speedup vs baseline: 1.4917x; 1.0543x over previous
#include <cuda_runtime.h>
#include <cuda_fp16.h>
#include <cstdint>
#include <cstddef>

#define NN 100000
#define NPAD 100096   // 782 * 128
#define NE 1600000
#define C 128
#define NB_SCAN 98    // ceil(NN / 1024)

#define GB_COUNT 1563    // ceil(NE/4 / 256)
#define GB_SPLIT 12500   // NN*C/4 / 256
#define GB_WPREP 384     // 3 * 128

// ---------------- scratch (device globals; zero-init at load) ----------------
__device__ int   g_deg[NN];      // invariant: zero at kernel_launch entry
__device__ int   g_ptr[NN + 1];
__device__ float g_invc[NN];
__device__ int   g_csr[NE];
__device__ int   g_epos[NE];
__device__ int   g_bsum[128];

__device__ __half g_xf16 [(size_t)NPAD * C];
__device__ __half g_h1f16[(size_t)NPAD * C];
__device__ __half g_aggf16[(size_t)NPAD * C];

// weights fp16, [n][k] transposed; layer1/2 K=256 (Wl||Wr), decoder K=128
__device__ __half g_w1[128 * 256];
__device__ __half g_w2[128 * 256];
__device__ __half g_wd[128 * 128];

// ---------------- helpers ----------------
__device__ __forceinline__ uint32_t s2u(const void* p) {
    uint32_t a;
    asm("{ .reg .u64 t; cvta.to.shared.u64 t, %1; cvt.u32.u64 %0, t; }" : "=r"(a) : "l"(p));
    return a;
}
__device__ __forceinline__ void ldsm4(uint32_t* r, uint32_t addr) {
    asm volatile("ldmatrix.sync.aligned.m8n8.x4.shared.b16 {%0,%1,%2,%3}, [%4];"
                 : "=r"(r[0]), "=r"(r[1]), "=r"(r[2]), "=r"(r[3]) : "r"(addr));
}
__device__ __forceinline__ void mmaf16(float* d, const uint32_t* a, const uint32_t* b) {
    asm volatile(
        "mma.sync.aligned.m16n8k16.row.col.f32.f16.f16.f32 "
        "{%0,%1,%2,%3}, {%4,%5,%6,%7}, {%8,%9}, {%0,%1,%2,%3};"
        : "+f"(d[0]), "+f"(d[1]), "+f"(d[2]), "+f"(d[3])
        : "r"(a[0]), "r"(a[1]), "r"(a[2]), "r"(a[3]), "r"(b[0]), "r"(b[1]));
}
__device__ __forceinline__ uint32_t swz64(uint32_t off) {
    return off ^ ((off >> 3) & 0x30u);
}
__device__ __forceinline__ void cp16(uint32_t saddr, const void* gaddr) {
    asm volatile("cp.async.cg.shared.global [%0], [%1], 16;" :: "r"(saddr), "l"(gaddr));
}
__device__ __forceinline__ void accv(float* a, uint4 v) {
    const __half2* h = (const __half2*)&v;
    #pragma unroll
    for (int q = 0; q < 4; q++) {
        float2 f = __half22float2(h[q]);
        a[2 * q]     += f.x;
        a[2 * q + 1] += f.y;
    }
}

// ---------------- fused prep: count (+epos) | split x->fp16 | weight transpose ----------------
__global__ void prep_kernel(const float* __restrict__ x, __half* __restrict__ xf16,
                            const float* __restrict__ W1l, const float* __restrict__ W1r,
                            const float* __restrict__ W2l, const float* __restrict__ W2r,
                            const float* __restrict__ Wd,
                            const int4* __restrict__ dst4) {
    const int bx = blockIdx.x;
    if (bx < GB_COUNT) {
        int i = bx * 256 + threadIdx.x;
        if (i < NE / 4) {
            int4 d = dst4[i];
            int4 p;
            p.x = atomicAdd(&g_deg[d.x], 1);
            p.y = atomicAdd(&g_deg[d.y], 1);
            p.z = atomicAdd(&g_deg[d.z], 1);
            p.w = atomicAdd(&g_deg[d.w], 1);
            ((int4*)g_epos)[i] = p;
        }
    } else if (bx < GB_COUNT + GB_SPLIT) {
        int i = (bx - GB_COUNT) * 256 + threadIdx.x;
        if (i < NN * C / 4) {
            float4 v = ((const float4*)x)[i];
            ((__half2*)xf16)[i * 2]     = __floats2half2_rn(v.x, v.y);
            ((__half2*)xf16)[i * 2 + 1] = __floats2half2_rn(v.z, v.w);
        }
    } else {
        const int idx = bx - GB_COUNT - GB_SPLIT;  // 0..383
        const int which = idx >> 7;
        const int n = idx & 127;
        const float* Wa; const float* Wb; __half* bh; int K;
        if (which == 0)      { Wa = W1l; Wb = W1r;     bh = g_w1; K = 256; }
        else if (which == 1) { Wa = W2l; Wb = W2r;     bh = g_w2; K = 256; }
        else                 { Wa = Wd;  Wb = nullptr; bh = g_wd; K = 128; }
        for (int k = threadIdx.x; k < K; k += blockDim.x) {
            float v = (k < C) ? Wa[k * C + n] : Wb[(k - C) * C + n];
            bh[n * K + k] = __float2half_rn(v);
        }
    }
}

// ---------------- CSR scans ----------------
__global__ void scan1_kernel() {
    __shared__ int wsum[32];
    const int lane = threadIdx.x & 31;
    const int wid  = threadIdx.x >> 5;
    int i = blockIdx.x * 1024 + threadIdx.x;
    int v = (i < NN) ? g_deg[i] : 0;
    int incl = v;
    #pragma unroll
    for (int o = 1; o < 32; o <<= 1) {
        int t = __shfl_up_sync(0xFFFFFFFFu, incl, o);
        if (lane >= o) incl += t;
    }
    if (lane == 31) wsum[wid] = incl;
    __syncthreads();
    if (wid == 0) {
        int ws = wsum[lane];
        int wi = ws;
        #pragma unroll
        for (int o = 1; o < 32; o <<= 1) {
            int t = __shfl_up_sync(0xFFFFFFFFu, wi, o);
            if (lane >= o) wi += t;
        }
        wsum[lane] = wi - ws;
    }
    __syncthreads();
    int excl = wsum[wid] + incl - v;
    if (i < NN) g_ptr[i] = excl;
    if (threadIdx.x == 1023) g_bsum[blockIdx.x] = excl + v;
}
__global__ void scan2_kernel() {
    __shared__ int ws[4];
    const int t = threadIdx.x;
    const int lane = t & 31;
    const int wid  = t >> 5;
    int v = (t < NB_SCAN) ? g_bsum[t] : 0;
    int incl = v;
    #pragma unroll
    for (int o = 1; o < 32; o <<= 1) {
        int s = __shfl_up_sync(0xFFFFFFFFu, incl, o);
        if (lane >= o) incl += s;
    }
    if (lane == 31) ws[wid] = incl;
    __syncthreads();
    int add = 0;
    #pragma unroll
    for (int w = 0; w < 4; w++) if (w < wid) add += ws[w];
    int excl = add + incl - v;
    __syncthreads();
    if (t < NB_SCAN) g_bsum[t] = excl;
}
__global__ void scan3_kernel() {
    int i = blockIdx.x * 1024 + threadIdx.x;
    if (i == 0) g_ptr[NN] = NE;
    if (i < NN) {
        g_ptr[i] += g_bsum[blockIdx.x];
        int d = g_deg[i];
        g_invc[i] = 1.0f / (float)(d < 1 ? 1 : d);
        g_deg[i] = 0;
    }
}
__global__ void build_kernel(const int4* __restrict__ src4, const int4* __restrict__ dst4) {
    int i = blockIdx.x * blockDim.x + threadIdx.x;
    if (i < NE / 4) {
        int4 s = src4[i];
        int4 d = dst4[i];
        int4 p = ((const int4*)g_epos)[i];
        g_csr[g_ptr[d.x] + p.x] = s.x;
        g_csr[g_ptr[d.y] + p.y] = s.y;
        g_csr[g_ptr[d.z] + p.z] = s.z;
        g_csr[g_ptr[d.w] + p.w] = s.w;
    }
}

// ---------------- aggregation: half-warp per node, uint4 lanes, 8-edge unroll ----------------
__global__ void agg_kernel(const __half* __restrict__ feat, __half* __restrict__ outp) {
    int g = (blockIdx.x * blockDim.x + threadIdx.x) >> 4;
    if (g >= NN) return;
    const int li = threadIdx.x & 15;
    int beg = g_ptr[g], end = g_ptr[g + 1];
    float acc[8];
    #pragma unroll
    for (int j = 0; j < 8; j++) acc[j] = 0.f;

    int e = beg;
    for (; e + 8 <= end; e += 8) {
        int idx[8];
        #pragma unroll
        for (int j = 0; j < 8; j++) idx[j] = g_csr[e + j];
        uint4 v[8];
        #pragma unroll
        for (int j = 0; j < 8; j++)
            v[j] = *((const uint4*)(feat + (size_t)idx[j] * C) + li);
        #pragma unroll
        for (int j = 0; j < 8; j++) accv(acc, v[j]);
    }
    for (; e < end; e++) {
        int s = g_csr[e];
        uint4 v = *((const uint4*)(feat + (size_t)s * C) + li);
        accv(acc, v);
    }

    const float iv = g_invc[g];
    uint4 o;
    __half2* oh = (__half2*)&o;
    #pragma unroll
    for (int q = 0; q < 4; q++)
        oh[q] = __floats2half2_rn(acc[2 * q] * iv, acc[2 * q + 1] * iv);
    *((uint4*)(outp + (size_t)g * C) + li) = o;
}

// ---------------- fp16 GEMM, 4-stage cp.async ----------------
// MODE 0: layer1 (K=256, A1=agg, A2=self) -> relu(acc + bias) -> fp16 global
// MODE 1: layer2+decoder fused (K=256 then K=128):
//   phase A: h2 = relu(agg@W2 + b2) -> SMEM (swz64 chunk layout)
//   phase B: out = alpha*(h2@Wd + bd) + (1-alpha)*x -> f32 global
// SMEM: MODE0: 4 stages (64KB). MODE1: 4 stages + 32KB h2 region (96KB).
template <int MODE>
__global__ __launch_bounds__(256, 2) void gemm_f16_kernel(
    const __half* __restrict__ A1, const __half* __restrict__ A2,
    const __half* __restrict__ B, const __half* __restrict__ Bd,
    const float* __restrict__ bias, const float* __restrict__ biasd,
    const float* __restrict__ xres, const float* __restrict__ alphaPtr,
    float* __restrict__ outF, __half* __restrict__ outH)
{
    constexpr int NCH = 8;          // K=256 mainloop
    constexpr int STG = 16384;
    extern __shared__ __align__(128) char smem[];
    const uint32_t us = s2u(smem);
    const uint32_t uh2 = us + 4 * STG;   // MODE 1 h2 region (32KB)

    const int tid  = threadIdx.x;
    const int wid  = tid >> 5;
    const int lane = tid & 31;
    const int m0   = blockIdx.x * 128;
    const int m0w  = (wid >> 1) * 32;
    const int n0w  = (wid & 1) * 64;

    const int lrow = tid >> 1;
    const int c16a = (tid & 1) * 2;

    float acc[2][8][4];
    #pragma unroll
    for (int i = 0; i < 2; i++)
        #pragma unroll
        for (int j = 0; j < 8; j++)
            #pragma unroll
            for (int q = 0; q < 4; q++) acc[i][j][q] = 0.f;

    auto issue = [&](int kc, int buf) {
        const __half* sA = (kc >= 4) ? A2 : A1;
        const char* pA = (const char*)sA + (size_t)(m0 + lrow) * 256 + (kc & 3) * 64;
        const char* pB = (const char*)B + (size_t)lrow * 512 + kc * 64;
        const uint32_t sb = us + buf * STG;
        #pragma unroll
        for (int j = 0; j < 2; j++) {
            const int c16 = c16a + j;
            const uint32_t so = swz64((uint32_t)(lrow * 64 + c16 * 16));
            cp16(sb + so,        pA + c16 * 16);
            cp16(sb + 8192 + so, pB + c16 * 16);
        }
        asm volatile("cp.async.commit_group;" ::: "memory");
    };

    issue(0, 0);
    issue(1, 1);
    issue(2, 2);
    #pragma unroll
    for (int kc = 0; kc < NCH; kc++) {
        if (kc + 2 < NCH) {
            asm volatile("cp.async.wait_group 2;" ::: "memory");
        } else if (kc + 1 < NCH) {
            asm volatile("cp.async.wait_group 1;" ::: "memory");
        } else {
            asm volatile("cp.async.wait_group 0;" ::: "memory");
        }
        __syncthreads();
        if (kc + 3 < NCH) issue(kc + 3, (kc + 3) & 3);
        const uint32_t sb = us + (kc & 3) * STG;
        #pragma unroll
        for (int s = 0; s < 2; s++) {
            uint32_t aF[2][4], bb[4][4];
            #pragma unroll
            for (int sub = 0; sub < 2; sub++) {
                const uint32_t off = swz64((uint32_t)(
                    (m0w + sub * 16 + (lane & 15)) * 64 + s * 32 + (lane >> 4) * 16));
                ldsm4(aF[sub], sb + off);
            }
            #pragma unroll
            for (int p = 0; p < 4; p++) {
                const uint32_t off = swz64((uint32_t)(
                    (n0w + p * 16 + (lane & 7) + ((lane >> 4) << 3)) * 64 +
                    s * 32 + ((lane >> 3) & 1) * 16));
                ldsm4(bb[p], sb + 8192 + off);
            }
            #pragma unroll
            for (int sub = 0; sub < 2; sub++)
                #pragma unroll
                for (int p = 0; p < 4; p++) {
                    mmaf16(acc[sub][p * 2 + 0], aF[sub], &bb[p][0]);
                    mmaf16(acc[sub][p * 2 + 1], aF[sub], &bb[p][2]);
                }
        }
    }

    // ---------------- relu + bias; MODE0 -> global, MODE1 -> SMEM h2 ----------------
    const int ccol0 = n0w + (lane & 3) * 2;
    #pragma unroll
    for (int sub = 0; sub < 2; sub++) {
        const int rbase = m0 + m0w + sub * 16 + (lane >> 2);
        const int rloc  = m0w + sub * 16 + (lane >> 2);
        #pragma unroll
        for (int f = 0; f < 8; f++) {
            const int col = ccol0 + f * 8;
            const float bx = bias[col], by = bias[col + 1];
            #pragma unroll
            for (int half = 0; half < 2; half++) {
                const int r  = rbase + half * 8;
                const int rl = rloc + half * 8;
                float vx = fmaxf(acc[sub][f][half * 2 + 0] + bx, 0.f);
                float vy = fmaxf(acc[sub][f][half * 2 + 1] + by, 0.f);
                __half2 hv = __floats2half2_rn(vx, vy);
                if (MODE == 0) {
                    if (r < NN)
                        *(__half2*)(outH + (size_t)r * C + col) = hv;
                } else {
                    // SMEM h2, chunk-major swz64: chunk = col>>5, byte = rl*64 + (col&31)*2
                    const uint32_t off = swz64((uint32_t)(rl * 64 + (col & 31) * 2));
                    *(__half2*)(smem + 4 * STG + (col >> 5) * 8192 + off) = hv;
                }
            }
        }
    }

    if (MODE == 1) {
        __syncthreads();   // h2 stores visible; stage buffers free

        // load Wd (32KB) into stage B-slots: chunk kc -> stage kc
        #pragma unroll
        for (int kc = 0; kc < 4; kc++) {
            const char* pB = (const char*)Bd + (size_t)lrow * 256 + kc * 64;
            const uint32_t sb = us + kc * STG;
            #pragma unroll
            for (int j = 0; j < 2; j++) {
                const int c16 = c16a + j;
                const uint32_t so = swz64((uint32_t)(lrow * 64 + c16 * 16));
                cp16(sb + 8192 + so, pB + c16 * 16);
            }
        }
        asm volatile("cp.async.commit_group;" ::: "memory");
        asm volatile("cp.async.wait_group 0;" ::: "memory");
        __syncthreads();

        float acc2[2][8][4];
        #pragma unroll
        for (int i = 0; i < 2; i++)
            #pragma unroll
            for (int j = 0; j < 8; j++)
                #pragma unroll
                for (int q = 0; q < 4; q++) acc2[i][j][q] = 0.f;

        #pragma unroll
        for (int kc = 0; kc < 4; kc++) {
            const uint32_t ab = uh2 + kc * 8192;
            const uint32_t sb = us + kc * STG;
            #pragma unroll
            for (int s = 0; s < 2; s++) {
                uint32_t aF[2][4], bb[4][4];
                #pragma unroll
                for (int sub = 0; sub < 2; sub++) {
                    const uint32_t off = swz64((uint32_t)(
                        (m0w + sub * 16 + (lane & 15)) * 64 + s * 32 + (lane >> 4) * 16));
                    ldsm4(aF[sub], ab + off);
                }
                #pragma unroll
                for (int p = 0; p < 4; p++) {
                    const uint32_t off = swz64((uint32_t)(
                        (n0w + p * 16 + (lane & 7) + ((lane >> 4) << 3)) * 64 +
                        s * 32 + ((lane >> 3) & 1) * 16));
                    ldsm4(bb[p], sb + 8192 + off);
                }
                #pragma unroll
                for (int sub = 0; sub < 2; sub++)
                    #pragma unroll
                    for (int p = 0; p < 4; p++) {
                        mmaf16(acc2[sub][p * 2 + 0], aF[sub], &bb[p][0]);
                        mmaf16(acc2[sub][p * 2 + 1], aF[sub], &bb[p][2]);
                    }
            }
        }

        const float al = *alphaPtr, om = 1.0f - al;
        #pragma unroll
        for (int sub = 0; sub < 2; sub++) {
            const int rbase = m0 + m0w + sub * 16 + (lane >> 2);
            #pragma unroll
            for (int f = 0; f < 8; f++) {
                const int col = ccol0 + f * 8;
                const float bx = biasd[col], by = biasd[col + 1];
                #pragma unroll
                for (int half = 0; half < 2; half++) {
                    const int r = rbase + half * 8;
                    if (r >= NN) continue;
                    const float2 xr = *(const float2*)(xres + (size_t)r * C + col);
                    float2 fv;
                    fv.x = al * (acc2[sub][f][half * 2 + 0] + bx) + om * xr.x;
                    fv.y = al * (acc2[sub][f][half * 2 + 1] + by) + om * xr.y;
                    *(float2*)(outF + (size_t)r * C + col) = fv;
                }
            }
        }
    }
}

// ---------------- launch ----------------
extern "C" void kernel_launch(void* const* d_in, const int* in_sizes, int n_in,
                              void* d_out, int out_size)
{
    const float* x    = (const float*)d_in[0];
    const int*   ei   = (const int*)  d_in[1];
    const float* W1l  = (const float*)d_in[2];
    const float* b1   = (const float*)d_in[3];
    const float* W1r  = (const float*)d_in[4];
    const float* W2l  = (const float*)d_in[5];
    const float* b2   = (const float*)d_in[6];
    const float* W2r  = (const float*)d_in[7];
    const float* Wd   = (const float*)d_in[8];
    const float* bd   = (const float*)d_in[9];
    const float* alph = (const float*)d_in[10];
    float* out = (float*)d_out;

    const int* src = ei;
    const int* dst = ei + NE;

    __half *xf16, *h1f16, *aggf16;
    __half *w1, *w2, *wd;
    cudaGetSymbolAddress((void**)&xf16,  g_xf16);
    cudaGetSymbolAddress((void**)&h1f16, g_h1f16);
    cudaGetSymbolAddress((void**)&aggf16,g_aggf16);
    cudaGetSymbolAddress((void**)&w1,    g_w1);
    cudaGetSymbolAddress((void**)&w2,    g_w2);
    cudaGetSymbolAddress((void**)&wd,    g_wd);

    const int SMEM_L1 = 4 * 16384;           // 64KB
    const int SMEM_L2 = 4 * 16384 + 32768;   // 96KB
    static bool attrSet = false;
    if (!attrSet) {
        cudaFuncSetAttribute(gemm_f16_kernel<0>, cudaFuncAttributeMaxDynamicSharedMemorySize, SMEM_L1);
        cudaFuncSetAttribute(gemm_f16_kernel<1>, cudaFuncAttributeMaxDynamicSharedMemorySize, SMEM_L2);
        attrSet = true;
    }

    const int TB = 256;
    const int gE4 = (NE / 4 + TB - 1) / TB;
    const int gAg = (NN * 16 + TB - 1) / TB;
    const int gM  = (NN + 127) / 128;

    // fused prep: count (atomics) || split x->fp16 || weight transpose
    prep_kernel<<<GB_COUNT + GB_SPLIT + GB_WPREP, TB>>>(
        x, xf16, W1l, W1r, W2l, W2r, Wd, (const int4*)dst);
    scan1_kernel<<<NB_SCAN, 1024>>>();
    scan2_kernel<<<1, 128>>>();
    scan3_kernel<<<NB_SCAN, 1024>>>();
    build_kernel<<<gE4, TB>>>((const int4*)src, (const int4*)dst);

    // layer 1 (K=256) -> h1
    agg_kernel<<<gAg, TB>>>(xf16, aggf16);
    gemm_f16_kernel<0><<<gM, 256, SMEM_L1>>>(aggf16, xf16, w1, nullptr,
                                             b1, nullptr, nullptr, nullptr,
                                             nullptr, h1f16);
    // layer 2 + decoder fused -> out
    agg_kernel<<<gAg, TB>>>(h1f16, aggf16);
    gemm_f16_kernel<1><<<gM, 256, SMEM_L2>>>(aggf16, h1f16, w2, wd,
                                             b2, bd, x, alph,
                                             out, nullptr);

    (void)in_sizes; (void)n_in; (void)out_size;
}